// round 1
// baseline (speedup 1.0000x reference)
#include <cuda_runtime.h>

#define Nn 50000
#define Hh 128
#define Ee 400000
#define Gg 8

// ---------------- scratch (static device globals; no allocation) ----------------
__device__ float d_h[Nn * Hh];      // node state
__device__ float d_tmp[Nn * Hh];    // enc hidden / u_pre / decoder hidden
__device__ float d_Ps[Nn * Hh];     // h @ W_src
__device__ float d_Pd[Nn * Hh];     // h @ W_dst
__device__ float d_t1[Nn * Hh];     // h @ U_h
__device__ float d_rm[Nn * Hh];     // sum of relu(pre) per dst node
__device__ int   d_cnt[Nn];
__device__ float d_invcnt[Nn];
__device__ float d_gsum[Gg * Hh];
__device__ float d_bcsum[Gg * Hh];
__device__ float d_gcnt[Gg];
__device__ float d_bccnt[Gg];
__device__ float d_gproj[Gg * Hh];  // x_graph @ U_g
__device__ float d_bcproj[Gg * Hh]; // x_BC @ U_bc + b_u1 + b_m2@U_a
__device__ float d_Wmu[Hh * Hh];    // W_m2 @ U_a

// ---------------- GEMM: C[M,128] = op(A[M,128]) @ B[128,128] (+epilogue) --------
#define F_RELU_A  1
#define F_SCALE_A 2
#define F_BIAS    4
#define F_RELU_O  8
#define F_ADDMAT  16
#define F_GRAPH   32

template<int FLAGS>
__global__ __launch_bounds__(256) void gemm_k128(
    const float* __restrict__ A, const float* __restrict__ B, float* __restrict__ C,
    const float* __restrict__ bias, const float* __restrict__ addmat,
    const int* __restrict__ batch, int M)
{
    __shared__ float As[16][132];
    __shared__ float Bs[16][128];
    const int tid = threadIdx.x;
    const int tx = tid & 15;        // N-dir (16 x 8 = 128)
    const int ty = tid >> 4;        // M-dir (16 x 8 = 128)
    const int row0 = blockIdx.x * 128;

    float acc[8][8];
#pragma unroll
    for (int i = 0; i < 8; i++)
#pragma unroll
        for (int j = 0; j < 8; j++) acc[i][j] = 0.f;

    const int lr = tid >> 2;          // 0..63
    const int lc = (tid & 3) * 4;     // 0,4,8,12

    for (int kk = 0; kk < 128; kk += 16) {
        // A tile (transposed into smem): rows row0..+127, cols kk..+15
#pragma unroll
        for (int p = 0; p < 2; p++) {
            int r = lr + p * 64;
            int grow = row0 + r; if (grow > M - 1) grow = M - 1;
            float4 v = *(const float4*)(A + (size_t)grow * Hh + kk + lc);
            if (FLAGS & F_RELU_A) {
                v.x = fmaxf(v.x, 0.f); v.y = fmaxf(v.y, 0.f);
                v.z = fmaxf(v.z, 0.f); v.w = fmaxf(v.w, 0.f);
            }
            if (FLAGS & F_SCALE_A) {
                float s = d_invcnt[grow];
                v.x *= s; v.y *= s; v.z *= s; v.w *= s;
            }
            As[lc + 0][r] = v.x; As[lc + 1][r] = v.y;
            As[lc + 2][r] = v.z; As[lc + 3][r] = v.w;
        }
        // B tile
        {
            int r = tid >> 5;             // 0..7
            int c = (tid & 31) * 4;       // 0..124
#pragma unroll
            for (int p = 0; p < 2; p++) {
                float4 v = *(const float4*)(B + (size_t)(kk + r + p * 8) * Hh + c);
                *(float4*)&Bs[r + p * 8][c] = v;
            }
        }
        __syncthreads();
#pragma unroll
        for (int k = 0; k < 16; k++) {
            float a[8], b[8];
            *(float4*)&a[0] = *(const float4*)&As[k][ty * 8];
            *(float4*)&a[4] = *(const float4*)&As[k][ty * 8 + 4];
            *(float4*)&b[0] = *(const float4*)&Bs[k][tx * 8];
            *(float4*)&b[4] = *(const float4*)&Bs[k][tx * 8 + 4];
#pragma unroll
            for (int i = 0; i < 8; i++)
#pragma unroll
                for (int j = 0; j < 8; j++)
                    acc[i][j] = fmaf(a[i], b[j], acc[i][j]);
        }
        __syncthreads();
    }

#pragma unroll
    for (int i = 0; i < 8; i++) {
        int grow = row0 + ty * 8 + i;
        if (grow >= M) continue;
        int g = 0;
        if (FLAGS & F_GRAPH) g = batch[grow];
#pragma unroll
        for (int j0 = 0; j0 < 8; j0 += 4) {
            int col = tx * 8 + j0;
            float4 v = make_float4(acc[i][j0], acc[i][j0 + 1], acc[i][j0 + 2], acc[i][j0 + 3]);
            if (FLAGS & F_BIAS) {
                float4 b4 = *(const float4*)(bias + col);
                v.x += b4.x; v.y += b4.y; v.z += b4.z; v.w += b4.w;
            }
            if (FLAGS & F_ADDMAT) {
                float4 m4 = *(const float4*)(addmat + (size_t)grow * Hh + col);
                v.x += m4.x; v.y += m4.y; v.z += m4.z; v.w += m4.w;
            }
            if (FLAGS & F_GRAPH) {
                float4 g4 = *(const float4*)(d_gproj  + g * Hh + col);
                float4 c4 = *(const float4*)(d_bcproj + g * Hh + col);
                v.x += g4.x + c4.x; v.y += g4.y + c4.y;
                v.z += g4.z + c4.z; v.w += g4.w + c4.w;
            }
            if (FLAGS & F_RELU_O) {
                v.x = fmaxf(v.x, 0.f); v.y = fmaxf(v.y, 0.f);
                v.z = fmaxf(v.z, 0.f); v.w = fmaxf(v.w, 0.f);
            }
            *(float4*)(C + (size_t)grow * Hh + col) = v;
        }
    }
}

// ---------------- encoder layer 1: d_tmp = relu([x|x_mask] @ W_e1 + b_e1) ------
__global__ __launch_bounds__(128) void enc1_kernel(
    const float* __restrict__ x, const float* __restrict__ xmask,
    const float* __restrict__ We1, const float* __restrict__ be1)
{
    __shared__ float sW[8 * Hh];
    __shared__ float sb[Hh];
    __shared__ float in[8];
    int f = threadIdx.x;
#pragma unroll
    for (int k = 0; k < 8; k++) sW[k * Hh + f] = We1[k * Hh + f];
    sb[f] = be1[f];
    __syncthreads();
    for (int v = blockIdx.x; v < Nn; v += gridDim.x) {
        if (f < 5)       in[f] = x[v * 5 + f];
        else if (f < 8)  in[f] = xmask[v * 3 + (f - 5)];
        __syncthreads();
        float s = sb[f];
#pragma unroll
        for (int k = 0; k < 8; k++) s = fmaf(in[k], sW[k * Hh + f], s);
        d_tmp[(size_t)v * Hh + f] = fmaxf(s, 0.f);
        __syncthreads();
    }
}

// ---------------- degree / counts ------------------------------------------
__global__ void zero_cnt_kernel() {
    int i = blockIdx.x * blockDim.x + threadIdx.x;
    if (i < Nn) d_cnt[i] = 0;
}
__global__ void deg_kernel(const int* __restrict__ ei) {
    for (int e = blockIdx.x * blockDim.x + threadIdx.x; e < Ee; e += gridDim.x * blockDim.x)
        atomicAdd(&d_cnt[ei[Ee + e]], 1);
}
__global__ void invcnt_kernel() {
    int i = blockIdx.x * blockDim.x + threadIdx.x;
    if (i < Nn) d_invcnt[i] = 1.0f / (float)(d_cnt[i] + 1);  // +1 self loop
}

// ---------------- graph stats ------------------------------------------------
__global__ void zero_stats_kernel() {
    int i = blockIdx.x * blockDim.x + threadIdx.x;
    if (i < Gg * Hh) { d_gsum[i] = 0.f; d_bcsum[i] = 0.f; }
    if (i < Gg) { d_gcnt[i] = 0.f; d_bccnt[i] = 0.f; }
}
__global__ void zero_gsum_kernel() {
    int i = blockIdx.x * blockDim.x + threadIdx.x;
    if (i < Gg * Hh) d_gsum[i] = 0.f;
}

// block = 128 threads (feature), handles 64 consecutive nodes (batch is sorted)
__global__ __launch_bounds__(128) void init_stats_kernel(
    const float* __restrict__ xmask, const int* __restrict__ batch)
{
    int f = threadIdx.x;
    int v0 = blockIdx.x * 64;
    if (v0 >= Nn) return;
    float acc = 0.f, accbc = 0.f, cacc = 0.f, bcacc = 0.f;
    int cur = batch[v0];
    for (int i = 0; i < 64; i++) {
        int v = v0 + i; if (v >= Nn) break;
        int g = batch[v];
        if (g != cur) {
            atomicAdd(&d_gsum[cur * Hh + f], acc);
            atomicAdd(&d_bcsum[cur * Hh + f], accbc);
            if (f == 0) { atomicAdd(&d_gcnt[cur], cacc); atomicAdd(&d_bccnt[cur], bcacc); }
            acc = accbc = cacc = bcacc = 0.f; cur = g;
        }
        float hv = d_h[(size_t)v * Hh + f];
        float bc = __ldg(xmask + v * 3 + 2);
        acc += hv; accbc += hv * bc;
        if (f == 0) { cacc += 1.f; bcacc += bc; }
    }
    atomicAdd(&d_gsum[cur * Hh + f], acc);
    atomicAdd(&d_bcsum[cur * Hh + f], accbc);
    if (f == 0) { atomicAdd(&d_gcnt[cur], cacc); atomicAdd(&d_bccnt[cur], bcacc); }
}

__global__ __launch_bounds__(128) void graph_sum_kernel(const int* __restrict__ batch)
{
    int f = threadIdx.x;
    int v0 = blockIdx.x * 64;
    if (v0 >= Nn) return;
    float acc = 0.f;
    int cur = batch[v0];
    for (int i = 0; i < 64; i++) {
        int v = v0 + i; if (v >= Nn) break;
        int g = batch[v];
        if (g != cur) { atomicAdd(&d_gsum[cur * Hh + f], acc); acc = 0.f; cur = g; }
        acc += d_h[(size_t)v * Hh + f];
    }
    atomicAdd(&d_gsum[cur * Hh + f], acc);
}

// g_proj[g] = (gsum[g]/max(cnt,1)) @ U_g   (U_g = W_u1 rows 256..383)
__global__ __launch_bounds__(128) void gproj_kernel(const float* __restrict__ Wu1)
{
    __shared__ float xg[Hh];
    int g = blockIdx.x, f = threadIdx.x;
    float c = fmaxf(d_gcnt[g], 1.f);
    xg[f] = d_gsum[g * Hh + f] / c;
    __syncthreads();
    float s = 0.f;
#pragma unroll 8
    for (int k = 0; k < Hh; k++) s = fmaf(xg[k], Wu1[(size_t)(256 + k) * Hh + f], s);
    d_gproj[g * Hh + f] = s;
}

// bc_proj2[g] = x_BC[g] @ U_bc + b_u1 + b_m2 @ U_a
__global__ __launch_bounds__(128) void bcproj_kernel(
    const float* __restrict__ Wu1, const float* __restrict__ bu1, const float* __restrict__ bm2)
{
    __shared__ float xbc[Hh];
    int g = blockIdx.x, f = threadIdx.x;
    float c = fmaxf(d_bccnt[g], 1.f);
    xbc[f] = d_bcsum[g * Hh + f] / c;
    __syncthreads();
    float s = bu1[f];
#pragma unroll 8
    for (int k = 0; k < Hh; k++) {
        s = fmaf(xbc[k],       Wu1[(size_t)(384 + k) * Hh + f], s);
        s = fmaf(__ldg(bm2 + k), Wu1[(size_t)(128 + k) * Hh + f], s);
    }
    d_bcproj[g * Hh + f] = s;
}

// Wmu = W_m2 @ U_a   (U_a = W_u1 rows 128..255)
__global__ __launch_bounds__(128) void wmu_kernel(
    const float* __restrict__ Wm2, const float* __restrict__ Wu1)
{
    __shared__ float row[Hh];
    int k = blockIdx.x, f = threadIdx.x;
    row[f] = Wm2[(size_t)k * Hh + f];
    __syncthreads();
    float s = 0.f;
#pragma unroll 8
    for (int j = 0; j < Hh; j++) s = fmaf(row[j], Wu1[(size_t)(128 + j) * Hh + f], s);
    d_Wmu[(size_t)k * Hh + f] = s;
}

// ---------------- self-loop init: rm[v] = relu(Ps[v] + Pd[v] + b_m1) ----------
__global__ void selfloop_kernel(const float* __restrict__ bm1)
{
    int i = blockIdx.x * blockDim.x + threadIdx.x;  // over Nn*32 float4s
    if (i >= Nn * 32) return;
    int f4 = i & 31;
    float4 ps = ((const float4*)d_Ps)[i];
    float4 pd = ((const float4*)d_Pd)[i];
    float4 b  = *(const float4*)(bm1 + f4 * 4);
    float4 v;
    v.x = fmaxf(ps.x + pd.x + b.x, 0.f);
    v.y = fmaxf(ps.y + pd.y + b.y, 0.f);
    v.z = fmaxf(ps.z + pd.z + b.z, 0.f);
    v.w = fmaxf(ps.w + pd.w + b.w, 0.f);
    ((float4*)d_rm)[i] = v;
}

// ---------------- edge scatter: rm[dst] += relu(Ps[src]+Pd[dst]+ea@Wea+b) -----
__device__ __forceinline__ void red_add_v4(float* p, float4 v) {
    asm volatile("red.global.add.v4.f32 [%0], {%1,%2,%3,%4};"
                 :: "l"(p), "f"(v.x), "f"(v.y), "f"(v.z), "f"(v.w) : "memory");
}

__global__ __launch_bounds__(256) void edge_scatter_kernel(
    const int* __restrict__ ei, const float* __restrict__ ea,
    const float* __restrict__ Wm1, const float* __restrict__ bm1)
{
    __shared__ float4 sW0[32], sW1[32], sW2[32], sB[32];
    int tid = threadIdx.x;
    if (tid < 32) {
        sW0[tid] = *(const float4*)(Wm1 + (size_t)256 * Hh + tid * 4);
        sW1[tid] = *(const float4*)(Wm1 + (size_t)257 * Hh + tid * 4);
        sW2[tid] = *(const float4*)(Wm1 + (size_t)258 * Hh + tid * 4);
        sB[tid]  = *(const float4*)(bm1 + tid * 4);
    }
    __syncthreads();
    int lane = tid & 31;
    int warp = blockIdx.x * (blockDim.x >> 5) + (tid >> 5);
    int nwarp = gridDim.x * (blockDim.x >> 5);
    float4 w0 = sW0[lane], w1 = sW1[lane], w2 = sW2[lane], bb = sB[lane];
    for (int e = warp; e < Ee; e += nwarp) {
        int s = __ldg(ei + e);
        int d = __ldg(ei + Ee + e);
        float a0 = __ldg(ea + 3 * e), a1 = __ldg(ea + 3 * e + 1), a2 = __ldg(ea + 3 * e + 2);
        float4 ps = *(const float4*)(d_Ps + (size_t)s * Hh + lane * 4);
        float4 pd = *(const float4*)(d_Pd + (size_t)d * Hh + lane * 4);
        float4 v;
        v.x = fmaxf(ps.x + pd.x + a0 * w0.x + a1 * w1.x + a2 * w2.x + bb.x, 0.f);
        v.y = fmaxf(ps.y + pd.y + a0 * w0.y + a1 * w1.y + a2 * w2.y + bb.y, 0.f);
        v.z = fmaxf(ps.z + pd.z + a0 * w0.z + a1 * w1.z + a2 * w2.z + bb.z, 0.f);
        v.w = fmaxf(ps.w + pd.w + a0 * w0.w + a1 * w1.w + a2 * w2.w + bb.w, 0.f);
        red_add_v4(d_rm + (size_t)d * Hh + lane * 4, v);
    }
}

// ---------------- decoder layer 2: out = d_tmp @ W_d2 + b_d2 (N=3) -----------
__global__ __launch_bounds__(256) void dec2_kernel(
    const float* __restrict__ Wd2, const float* __restrict__ bd2, float* __restrict__ out)
{
    int gt = blockIdx.x * blockDim.x + threadIdx.x;
    int w = gt >> 5, lane = gt & 31;
    if (w >= Nn) return;
    float4 v = ((const float4*)d_tmp)[(size_t)w * 32 + lane];
    float s0 = 0.f, s1 = 0.f, s2 = 0.f;
    int k0 = lane * 4;
    float av[4] = {v.x, v.y, v.z, v.w};
#pragma unroll
    for (int i = 0; i < 4; i++) {
        int k = k0 + i;
        float a = av[i];
        s0 = fmaf(a, __ldg(Wd2 + k * 3 + 0), s0);
        s1 = fmaf(a, __ldg(Wd2 + k * 3 + 1), s1);
        s2 = fmaf(a, __ldg(Wd2 + k * 3 + 2), s2);
    }
#pragma unroll
    for (int off = 16; off; off >>= 1) {
        s0 += __shfl_xor_sync(0xffffffffu, s0, off);
        s1 += __shfl_xor_sync(0xffffffffu, s1, off);
        s2 += __shfl_xor_sync(0xffffffffu, s2, off);
    }
    if (lane == 0) {
        out[w * 3 + 0] = s0 + __ldg(bd2 + 0);
        out[w * 3 + 1] = s1 + __ldg(bd2 + 1);
        out[w * 3 + 2] = s2 + __ldg(bd2 + 2);
    }
}

// ---------------- host orchestration ----------------------------------------
extern "C" void kernel_launch(void* const* d_in, const int* in_sizes, int n_in,
                              void* d_out, int out_size)
{
    const float* x     = (const float*)d_in[0];
    const float* xmask = (const float*)d_in[1];
    const float* ea    = (const float*)d_in[2];
    // d_in[3] = pos (unused by reference)
    const float* We1 = (const float*)d_in[4];
    const float* be1 = (const float*)d_in[5];
    const float* We2 = (const float*)d_in[6];
    const float* be2 = (const float*)d_in[7];
    const float* Wm1 = (const float*)d_in[8];
    const float* bm1 = (const float*)d_in[9];
    const float* Wm2 = (const float*)d_in[10];
    const float* bm2 = (const float*)d_in[11];
    const float* Wu1 = (const float*)d_in[12];
    const float* bu1 = (const float*)d_in[13];
    const float* Wu2 = (const float*)d_in[14];
    const float* bu2 = (const float*)d_in[15];
    const float* Wd1 = (const float*)d_in[16];
    const float* bd1 = (const float*)d_in[17];
    const float* Wd2 = (const float*)d_in[18];
    const float* bd2 = (const float*)d_in[19];
    const int*   ei    = (const int*)d_in[20];
    const int*   batch = (const int*)d_in[21];
    float* out = (float*)d_out;

    float *p_h, *p_tmp, *p_Ps, *p_Pd, *p_t1, *p_rm, *p_Wmu;
    cudaGetSymbolAddress((void**)&p_h,   d_h);
    cudaGetSymbolAddress((void**)&p_tmp, d_tmp);
    cudaGetSymbolAddress((void**)&p_Ps,  d_Ps);
    cudaGetSymbolAddress((void**)&p_Pd,  d_Pd);
    cudaGetSymbolAddress((void**)&p_t1,  d_t1);
    cudaGetSymbolAddress((void**)&p_rm,  d_rm);
    cudaGetSymbolAddress((void**)&p_Wmu, d_Wmu);

    const int GB = (Nn + 127) / 128;   // 391 GEMM blocks

    // encoder
    enc1_kernel<<<2048, 128>>>(x, xmask, We1, be1);
    gemm_k128<F_BIAS><<<GB, 256>>>(p_tmp, We2, p_h, be2, nullptr, nullptr, Nn);

    // degrees + inverse counts (includes self loop)
    zero_cnt_kernel<<<(Nn + 255) / 256, 256>>>();
    deg_kernel<<<1024, 256>>>(ei);
    invcnt_kernel<<<(Nn + 255) / 256, 256>>>();

    // graph statistics from h0 (x_graph, x_BC) + constant projections
    zero_stats_kernel<<<(Gg * Hh + 255) / 256, 256>>>();
    init_stats_kernel<<<(Nn + 63) / 64, 128>>>(xmask, batch);
    gproj_kernel<<<Gg, 128>>>(Wu1);
    bcproj_kernel<<<Gg, 128>>>(Wu1, bu1, bm2);
    wmu_kernel<<<Hh, 128>>>(Wm2, Wu1);

    // message-passing repeats
    for (int r = 0; r < 3; r++) {
        gemm_k128<0><<<GB, 256>>>(p_h, Wm1,                      p_Ps, nullptr, nullptr, nullptr, Nn);
        gemm_k128<0><<<GB, 256>>>(p_h, Wm1 + (size_t)128 * Hh,   p_Pd, nullptr, nullptr, nullptr, Nn);
        gemm_k128<0><<<GB, 256>>>(p_h, Wu1,                      p_t1, nullptr, nullptr, nullptr, Nn);
        selfloop_kernel<<<(Nn * 32 + 255) / 256, 256>>>(bm1);
        edge_scatter_kernel<<<2048, 256>>>(ei, ea, Wm1, bm1);
        // u = t1 + (rm*invcnt)@Wmu + gproj[batch] + bcproj[batch]
        gemm_k128<F_SCALE_A | F_ADDMAT | F_GRAPH><<<GB, 256>>>(
            p_rm, p_Wmu, p_tmp, nullptr, p_t1, batch, Nn);
        // h = h + relu(u)@W_u2 + b_u2
        gemm_k128<F_RELU_A | F_BIAS | F_ADDMAT><<<GB, 256>>>(
            p_tmp, Wu2, p_h, bu2, p_h, nullptr, Nn);
        if (r < 2) {
            zero_gsum_kernel<<<(Gg * Hh + 255) / 256, 256>>>();
            graph_sum_kernel<<<(Nn + 63) / 64, 128>>>(batch);
            gproj_kernel<<<Gg, 128>>>(Wu1);
        }
    }

    // decoder
    gemm_k128<F_BIAS | F_RELU_O><<<GB, 256>>>(p_h, Wd1, p_tmp, bd1, nullptr, nullptr, Nn);
    dec2_kernel<<<(Nn * 32 + 255) / 256, 256>>>(Wd2, bd2, out);
}

// round 3
// speedup vs baseline: 1.4377x; 1.4377x over previous
#include <cuda_runtime.h>
#include <cuda_bf16.h>

#define Nn 50000
#define Hh 128
#define Ee 400000
#define Gg 8
#define NB 391            // ceil(Nn/128)
typedef __nv_bfloat16 bf16;
typedef unsigned int u32;

// ---------------- scratch (static device globals; no allocation) ----------------
__device__ float d_h[Nn * Hh];
__device__ float d_tmp[Nn * Hh];
__device__ float d_cat[3 * Nn * Hh];        // Ps | Pd | t1
__device__ float d_rm[Nn * Hh];
__device__ bf16  d_a16h[Nn * Hh], d_a16l[Nn * Hh];   // generic A staging
__device__ bf16  d_h16h[Nn * Hh], d_h16l[Nn * Hh];   // h split
__device__ bf16  d_imgh[7 * 128 * 128], d_imgl[7 * 128 * 128]; // W^T images [n][k]
__device__ int   d_cnt[Nn];
__device__ float d_invcnt[Nn];
__device__ float d_gsum[Gg * Hh], d_bcsum[Gg * Hh], d_gcnt[Gg], d_bccnt[Gg];
__device__ float d_gproj[Gg * Hh], d_bcproj[Gg * Hh];
__device__ float d_Wmu[Hh * Hh];

// ---------------- helpers ----------------
__device__ __forceinline__ u32 smem_u32(const void* p) {
    u32 a;
    asm("{ .reg .u64 t; cvta.to.shared.u64 t, %1; cvt.u32.u64 %0, t; }" : "=r"(a) : "l"(p));
    return a;
}
__device__ __forceinline__ void ldsm_x4(u32* r, u32 addr) {
    asm volatile("ldmatrix.sync.aligned.m8n8.x4.shared.b16 {%0,%1,%2,%3}, [%4];"
                 : "=r"(r[0]), "=r"(r[1]), "=r"(r[2]), "=r"(r[3]) : "r"(addr));
}
__device__ __forceinline__ void ldsm_x2(u32* r, u32 addr) {
    asm volatile("ldmatrix.sync.aligned.m8n8.x2.shared.b16 {%0,%1}, [%2];"
                 : "=r"(r[0]), "=r"(r[1]) : "r"(addr));
}
__device__ __forceinline__ void mma16816(float* c, const u32* a, const u32* b) {
    asm volatile("mma.sync.aligned.m16n8k16.row.col.f32.bf16.bf16.f32 "
                 "{%0,%1,%2,%3}, {%4,%5,%6,%7}, {%8,%9}, {%0,%1,%2,%3};"
                 : "+f"(c[0]), "+f"(c[1]), "+f"(c[2]), "+f"(c[3])
                 : "r"(a[0]), "r"(a[1]), "r"(a[2]), "r"(a[3]), "r"(b[0]), "r"(b[1]));
}
__device__ __forceinline__ void split2(float v, unsigned short& h, unsigned short& l) {
    bf16 hh = __float2bfloat16(v);
    bf16 ll = __float2bfloat16(v - __bfloat162float(hh));
    h = __bfloat16_as_ushort(hh);
    l = __bfloat16_as_ushort(ll);
}
__device__ __forceinline__ u32 pack2(float a, float b) {
    unsigned short ha, la, hb, lb;
    bf16 x = __float2bfloat16(a); ha = __bfloat16_as_ushort(x);
    bf16 y = __float2bfloat16(b); hb = __bfloat16_as_ushort(y);
    (void)la; (void)lb;
    return (u32)ha | ((u32)hb << 16);
}

// ---------------- tensor-core GEMM via mma.sync -------------------------------
#define F_BIAS   1
#define F_ADDMAT 2
#define F_GRAPH  4
#define F_RELU_O 8
#define F_WRITEC 16
#define F_EMIT16 32

#define PAD_B 272               // bytes per padded row (136 bf16)
#define SM_A_HI 0
#define SM_A_LO (128 * PAD_B)
#define SM_B_HI (2 * 128 * PAD_B)
#define SM_B_LO (3 * 128 * PAD_B)
#define SMEMSZ  (4 * 128 * PAD_B)   // 139264 B

template<int FLAGS>
__global__ void __launch_bounds__(256, 1) gemm_tc(
    const bf16* __restrict__ Ahi, const bf16* __restrict__ Alo,
    const bf16* __restrict__ Bhi, const bf16* __restrict__ Blo,
    float* __restrict__ C, const float* __restrict__ bias,
    const float* __restrict__ addmat, const int* __restrict__ batch,
    bf16* __restrict__ Ehi, bf16* __restrict__ Elo, int M)
{
    extern __shared__ char smem[];
    const u32 sb = smem_u32(smem);
    const int tid = threadIdx.x;
    const int wid = tid >> 5, lane = tid & 31;
    const int row0 = blockIdx.x * 128;
    const int yt = blockIdx.y;
    const bf16* bhi = Bhi + yt * 16384;
    const bf16* blo = Blo + yt * 16384;
    float* Cy = C + (size_t)yt * M * Hh;

    // stage A (split, clamped rows) and B into padded smem
#pragma unroll
    for (int i = 0; i < 8; i++) {
        int idx = tid + i * 256;          // 0..2047 chunks of 16B
        int r = idx >> 4, c = idx & 15;
        int grow = row0 + r; if (grow > M - 1) grow = M - 1;
        *(uint4*)(smem + SM_A_HI + r * PAD_B + c * 16) = ((const uint4*)(Ahi + (size_t)grow * Hh))[c];
        *(uint4*)(smem + SM_A_LO + r * PAD_B + c * 16) = ((const uint4*)(Alo + (size_t)grow * Hh))[c];
        *(uint4*)(smem + SM_B_HI + r * PAD_B + c * 16) = ((const uint4*)bhi)[idx];
        *(uint4*)(smem + SM_B_LO + r * PAD_B + c * 16) = ((const uint4*)blo)[idx];
    }
    __syncthreads();

    float acc[16][4];
#pragma unroll
    for (int n = 0; n < 16; n++)
#pragma unroll
        for (int j = 0; j < 4; j++) acc[n][j] = 0.f;

    // lane addressing
    const int arow = wid * 16 + (lane & 15);
    const u32 aoff = (u32)(arow * PAD_B + (lane >> 4) * 16);
    const int brow = lane & 7;
    const u32 boff_in = (u32)(brow * PAD_B + ((lane >> 3) & 1) * 16);

    for (int ks = 0; ks < 8; ks++) {
        u32 ah[4], al[4];
        u32 kbyte = (u32)(ks * 32);
        ldsm_x4(ah, sb + SM_A_HI + aoff + kbyte);
        ldsm_x4(al, sb + SM_A_LO + aoff + kbyte);
#pragma unroll
        for (int nt = 0; nt < 16; nt++) {
            u32 bh[2], bl[2];
            u32 bo = (u32)(nt * 8 * PAD_B) + boff_in + kbyte;
            ldsm_x2(bh, sb + SM_B_HI + bo);
            ldsm_x2(bl, sb + SM_B_LO + bo);
            mma16816(acc[nt], ah, bh);
            mma16816(acc[nt], al, bh);
            mma16816(acc[nt], ah, bl);
        }
    }

    // epilogue straight from registers
    const int rbase = row0 + wid * 16 + (lane >> 2);
    const int cbase = (lane & 3) * 2;
#pragma unroll
    for (int half = 0; half < 2; half++) {
        int grow = rbase + half * 8;
        if (grow >= M) continue;
        int g = 0;
        if (FLAGS & F_GRAPH) g = batch[grow];
#pragma unroll
        for (int nt = 0; nt < 16; nt++) {
            int col = nt * 8 + cbase;
            float v0 = acc[nt][half * 2 + 0];
            float v1 = acc[nt][half * 2 + 1];
            if (FLAGS & F_BIAS) {
                float2 b2 = *(const float2*)(bias + col);
                v0 += b2.x; v1 += b2.y;
            }
            if (FLAGS & F_ADDMAT) {
                float2 m2 = *(const float2*)(addmat + (size_t)grow * Hh + col);
                v0 += m2.x; v1 += m2.y;
            }
            if (FLAGS & F_GRAPH) {
                float2 g2 = *(const float2*)(d_gproj + g * Hh + col);
                float2 c2 = *(const float2*)(d_bcproj + g * Hh + col);
                v0 += g2.x + c2.x; v1 += g2.y + c2.y;
            }
            if (FLAGS & F_RELU_O) { v0 = fmaxf(v0, 0.f); v1 = fmaxf(v1, 0.f); }
            if (FLAGS & F_WRITEC)
                *(float2*)(Cy + (size_t)grow * Hh + col) = make_float2(v0, v1);
            if (FLAGS & F_EMIT16) {
                unsigned short h0, l0, h1, l1;
                split2(v0, h0, l0); split2(v1, h1, l1);
                *(u32*)(Ehi + (size_t)grow * Hh + col) = (u32)h0 | ((u32)h1 << 16);
                *(u32*)(Elo + (size_t)grow * Hh + col) = (u32)l0 | ((u32)l1 << 16);
            }
        }
    }
}

// ---------------- weight prep: W^T split into [n][k] images -------------------
__global__ void __launch_bounds__(256) prep_weights(
    const float* __restrict__ We2, const float* __restrict__ Wm1,
    const float* __restrict__ Wu1, const float* __restrict__ Wu2,
    const float* __restrict__ Wd1)
{
    int tile = blockIdx.y;
    int idx = blockIdx.x * 256 + threadIdx.x;   // 0..16383
    int n = idx >> 7, k = idx & 127;
    float v = 0.f;
    switch (tile) {
        case 0: v = We2[(size_t)k * Hh + n]; break;
        case 1: v = Wm1[(size_t)k * Hh + n]; break;           // W_m1 src half
        case 2: v = Wm1[(size_t)(128 + k) * Hh + n]; break;   // W_m1 dst half
        case 3: v = Wu1[(size_t)k * Hh + n]; break;           // U_h
        case 4: v = d_Wmu[(size_t)k * Hh + n]; break;         // W_m2 @ U_a
        case 5: v = Wu2[(size_t)k * Hh + n]; break;
        case 6: v = Wd1[(size_t)k * Hh + n]; break;
    }
    unsigned short h, l;
    split2(v, h, l);
    d_imgh[tile * 16384 + n * 128 + k] = __ushort_as_bfloat16(h);
    d_imgl[tile * 16384 + n * 128 + k] = __ushort_as_bfloat16(l);
}

// ---------------- encoder layer 1 (emits split bf16 hidden) -------------------
__global__ void __launch_bounds__(128) enc1_kernel(
    const float* __restrict__ x, const float* __restrict__ xmask,
    const float* __restrict__ We1, const float* __restrict__ be1)
{
    __shared__ float sW[8 * Hh];
    __shared__ float sb_[Hh];
    __shared__ float in[8];
    int f = threadIdx.x;
#pragma unroll
    for (int k = 0; k < 8; k++) sW[k * Hh + f] = We1[k * Hh + f];
    sb_[f] = be1[f];
    __syncthreads();
    for (int v = blockIdx.x; v < Nn; v += gridDim.x) {
        if (f < 5)      in[f] = x[v * 5 + f];
        else if (f < 8) in[f] = xmask[v * 3 + (f - 5)];
        __syncthreads();
        float s = sb_[f];
#pragma unroll
        for (int k = 0; k < 8; k++) s = fmaf(in[k], sW[k * Hh + f], s);
        s = fmaxf(s, 0.f);
        unsigned short h, l;
        split2(s, h, l);
        d_a16h[(size_t)v * Hh + f] = __ushort_as_bfloat16(h);
        d_a16l[(size_t)v * Hh + f] = __ushort_as_bfloat16(l);
        __syncthreads();
    }
}

// ---------------- degree / counts ----------------------------------------------
__global__ void zero_cnt_kernel() {
    int i = blockIdx.x * blockDim.x + threadIdx.x;
    if (i < Nn) d_cnt[i] = 0;
}
__global__ void deg_kernel(const int* __restrict__ ei) {
    for (int e = blockIdx.x * blockDim.x + threadIdx.x; e < Ee; e += gridDim.x * blockDim.x)
        atomicAdd(&d_cnt[ei[Ee + e]], 1);
}
__global__ void invcnt_kernel() {
    int i = blockIdx.x * blockDim.x + threadIdx.x;
    if (i < Nn) d_invcnt[i] = 1.0f / (float)(d_cnt[i] + 1);
}

// ---------------- graph stats ---------------------------------------------------
__global__ void zero_stats_kernel() {
    int i = blockIdx.x * blockDim.x + threadIdx.x;
    if (i < Gg * Hh) { d_gsum[i] = 0.f; d_bcsum[i] = 0.f; }
    if (i < Gg) { d_gcnt[i] = 0.f; d_bccnt[i] = 0.f; }
}
__global__ void zero_gsum_kernel() {
    int i = blockIdx.x * blockDim.x + threadIdx.x;
    if (i < Gg * Hh) d_gsum[i] = 0.f;
}
__global__ void __launch_bounds__(128) init_stats_kernel(
    const float* __restrict__ xmask, const int* __restrict__ batch)
{
    int f = threadIdx.x;
    int v0 = blockIdx.x * 64;
    if (v0 >= Nn) return;
    float acc = 0.f, accbc = 0.f, cacc = 0.f, bcacc = 0.f;
    int cur = batch[v0];
    for (int i = 0; i < 64; i++) {
        int v = v0 + i; if (v >= Nn) break;
        int g = batch[v];
        if (g != cur) {
            atomicAdd(&d_gsum[cur * Hh + f], acc);
            atomicAdd(&d_bcsum[cur * Hh + f], accbc);
            if (f == 0) { atomicAdd(&d_gcnt[cur], cacc); atomicAdd(&d_bccnt[cur], bcacc); }
            acc = accbc = cacc = bcacc = 0.f; cur = g;
        }
        float hv = d_h[(size_t)v * Hh + f];
        float bc = __ldg(xmask + v * 3 + 2);
        acc += hv; accbc += hv * bc;
        if (f == 0) { cacc += 1.f; bcacc += bc; }
    }
    atomicAdd(&d_gsum[cur * Hh + f], acc);
    atomicAdd(&d_bcsum[cur * Hh + f], accbc);
    if (f == 0) { atomicAdd(&d_gcnt[cur], cacc); atomicAdd(&d_bccnt[cur], bcacc); }
}
__global__ void __launch_bounds__(128) graph_sum_kernel(const int* __restrict__ batch)
{
    int f = threadIdx.x;
    int v0 = blockIdx.x * 64;
    if (v0 >= Nn) return;
    float acc = 0.f;
    int cur = batch[v0];
    for (int i = 0; i < 64; i++) {
        int v = v0 + i; if (v >= Nn) break;
        int g = batch[v];
        if (g != cur) { atomicAdd(&d_gsum[cur * Hh + f], acc); acc = 0.f; cur = g; }
        acc += d_h[(size_t)v * Hh + f];
    }
    atomicAdd(&d_gsum[cur * Hh + f], acc);
}
__global__ void __launch_bounds__(128) gproj_kernel(const float* __restrict__ Wu1)
{
    __shared__ float xg[Hh];
    int g = blockIdx.x, f = threadIdx.x;
    float c = fmaxf(d_gcnt[g], 1.f);
    xg[f] = d_gsum[g * Hh + f] / c;
    __syncthreads();
    float s = 0.f;
#pragma unroll 8
    for (int k = 0; k < Hh; k++) s = fmaf(xg[k], Wu1[(size_t)(256 + k) * Hh + f], s);
    d_gproj[g * Hh + f] = s;
}
__global__ void __launch_bounds__(128) bcproj_kernel(
    const float* __restrict__ Wu1, const float* __restrict__ bu1, const float* __restrict__ bm2)
{
    __shared__ float xbc[Hh];
    int g = blockIdx.x, f = threadIdx.x;
    float c = fmaxf(d_bccnt[g], 1.f);
    xbc[f] = d_bcsum[g * Hh + f] / c;
    __syncthreads();
    float s = bu1[f];
#pragma unroll 8
    for (int k = 0; k < Hh; k++) {
        s = fmaf(xbc[k],         Wu1[(size_t)(384 + k) * Hh + f], s);
        s = fmaf(__ldg(bm2 + k), Wu1[(size_t)(128 + k) * Hh + f], s);
    }
    d_bcproj[g * Hh + f] = s;
}
__global__ void __launch_bounds__(128) wmu_kernel(
    const float* __restrict__ Wm2, const float* __restrict__ Wu1)
{
    __shared__ float row[Hh];
    int k = blockIdx.x, f = threadIdx.x;
    row[f] = Wm2[(size_t)k * Hh + f];
    __syncthreads();
    float s = 0.f;
#pragma unroll 8
    for (int j = 0; j < Hh; j++) s = fmaf(row[j], Wu1[(size_t)(128 + j) * Hh + f], s);
    d_Wmu[(size_t)k * Hh + f] = s;
}

// ---------------- self-loop + edge scatter --------------------------------------
__global__ void selfloop_kernel(const float* __restrict__ bm1)
{
    int i = blockIdx.x * blockDim.x + threadIdx.x;
    if (i >= Nn * 32) return;
    int f4 = i & 31;
    const float4* PS = (const float4*)d_cat;
    const float4* PD = PS + (size_t)Nn * 32;
    float4 ps = PS[i];
    float4 pd = PD[i];
    float4 b = *(const float4*)(bm1 + f4 * 4);
    float4 v;
    v.x = fmaxf(ps.x + pd.x + b.x, 0.f);
    v.y = fmaxf(ps.y + pd.y + b.y, 0.f);
    v.z = fmaxf(ps.z + pd.z + b.z, 0.f);
    v.w = fmaxf(ps.w + pd.w + b.w, 0.f);
    ((float4*)d_rm)[i] = v;
}

__device__ __forceinline__ void red_add_v4(float* p, float4 v) {
    asm volatile("red.global.add.v4.f32 [%0], {%1,%2,%3,%4};"
                 :: "l"(p), "f"(v.x), "f"(v.y), "f"(v.z), "f"(v.w) : "memory");
}
__global__ void __launch_bounds__(256) edge_scatter_kernel(
    const int* __restrict__ ei, const float* __restrict__ ea,
    const float* __restrict__ Wm1, const float* __restrict__ bm1)
{
    __shared__ float4 sW0[32], sW1[32], sW2[32], sB[32];
    int tid = threadIdx.x;
    if (tid < 32) {
        sW0[tid] = *(const float4*)(Wm1 + (size_t)256 * Hh + tid * 4);
        sW1[tid] = *(const float4*)(Wm1 + (size_t)257 * Hh + tid * 4);
        sW2[tid] = *(const float4*)(Wm1 + (size_t)258 * Hh + tid * 4);
        sB[tid]  = *(const float4*)(bm1 + tid * 4);
    }
    __syncthreads();
    int lane = tid & 31;
    int warp = blockIdx.x * (blockDim.x >> 5) + (tid >> 5);
    int nwarp = gridDim.x * (blockDim.x >> 5);
    float4 w0 = sW0[lane], w1 = sW1[lane], w2 = sW2[lane], bb = sB[lane];
    const float* Ps = d_cat;
    const float* Pd = d_cat + (size_t)Nn * Hh;
    for (int e = warp; e < Ee; e += nwarp) {
        int s = __ldg(ei + e);
        int d = __ldg(ei + Ee + e);
        float a0 = __ldg(ea + 3 * e), a1 = __ldg(ea + 3 * e + 1), a2 = __ldg(ea + 3 * e + 2);
        float4 ps = *(const float4*)(Ps + (size_t)s * Hh + lane * 4);
        float4 pd = *(const float4*)(Pd + (size_t)d * Hh + lane * 4);
        float4 v;
        v.x = fmaxf(ps.x + pd.x + a0 * w0.x + a1 * w1.x + a2 * w2.x + bb.x, 0.f);
        v.y = fmaxf(ps.y + pd.y + a0 * w0.y + a1 * w1.y + a2 * w2.y + bb.y, 0.f);
        v.z = fmaxf(ps.z + pd.z + a0 * w0.z + a1 * w1.z + a2 * w2.z + bb.z, 0.f);
        v.w = fmaxf(ps.w + pd.w + a0 * w0.w + a1 * w1.w + a2 * w2.w + bb.w, 0.f);
        red_add_v4(d_rm + (size_t)d * Hh + lane * 4, v);
    }
}

// ---------------- rm conversion: a16 = split(rm * invcnt) ------------------------
__global__ void conv_rm_kernel()
{
    int i = blockIdx.x * blockDim.x + threadIdx.x;
    if (i >= Nn * 32) return;
    int row = i >> 5;
    float s = d_invcnt[row];
    float4 v = ((const float4*)d_rm)[i];
    v.x *= s; v.y *= s; v.z *= s; v.w *= s;
    ushort4 hv, lv;
    split2(v.x, hv.x, lv.x); split2(v.y, hv.y, lv.y);
    split2(v.z, hv.z, lv.z); split2(v.w, hv.w, lv.w);
    ((ushort4*)d_a16h)[i] = hv;
    ((ushort4*)d_a16l)[i] = lv;
}

// ---------------- decoder layer 2 -------------------------------------------------
__global__ void __launch_bounds__(256) dec2_kernel(
    const float* __restrict__ Wd2, const float* __restrict__ bd2, float* __restrict__ out)
{
    int gt = blockIdx.x * blockDim.x + threadIdx.x;
    int w = gt >> 5, lane = gt & 31;
    if (w >= Nn) return;
    float4 v = ((const float4*)d_tmp)[(size_t)w * 32 + lane];
    float s0 = 0.f, s1 = 0.f, s2 = 0.f;
    int k0 = lane * 4;
    float av[4] = {v.x, v.y, v.z, v.w};
#pragma unroll
    for (int i = 0; i < 4; i++) {
        int k = k0 + i;
        float a = av[i];
        s0 = fmaf(a, __ldg(Wd2 + k * 3 + 0), s0);
        s1 = fmaf(a, __ldg(Wd2 + k * 3 + 1), s1);
        s2 = fmaf(a, __ldg(Wd2 + k * 3 + 2), s2);
    }
#pragma unroll
    for (int off = 16; off; off >>= 1) {
        s0 += __shfl_xor_sync(0xffffffffu, s0, off);
        s1 += __shfl_xor_sync(0xffffffffu, s1, off);
        s2 += __shfl_xor_sync(0xffffffffu, s2, off);
    }
    if (lane == 0) {
        out[w * 3 + 0] = s0 + __ldg(bd2 + 0);
        out[w * 3 + 1] = s1 + __ldg(bd2 + 1);
        out[w * 3 + 2] = s2 + __ldg(bd2 + 2);
    }
}

// ---------------- host orchestration ----------------------------------------------
extern "C" void kernel_launch(void* const* d_in, const int* in_sizes, int n_in,
                              void* d_out, int out_size)
{
    const float* x     = (const float*)d_in[0];
    const float* xmask = (const float*)d_in[1];
    const float* ea    = (const float*)d_in[2];
    const float* We1 = (const float*)d_in[4];
    const float* be1 = (const float*)d_in[5];
    const float* We2 = (const float*)d_in[6];
    const float* be2 = (const float*)d_in[7];
    const float* Wm1 = (const float*)d_in[8];
    const float* bm1 = (const float*)d_in[9];
    const float* Wm2 = (const float*)d_in[10];
    const float* bm2 = (const float*)d_in[11];
    const float* Wu1 = (const float*)d_in[12];
    const float* bu1 = (const float*)d_in[13];
    const float* Wu2 = (const float*)d_in[14];
    const float* bu2 = (const float*)d_in[15];
    const float* Wd1 = (const float*)d_in[16];
    const float* bd1 = (const float*)d_in[17];
    const float* Wd2 = (const float*)d_in[18];
    const float* bd2 = (const float*)d_in[19];
    const int*   ei    = (const int*)d_in[20];
    const int*   batch = (const int*)d_in[21];
    float* out = (float*)d_out;

    float *p_h, *p_tmp, *p_cat;
    bf16 *p_a16h, *p_a16l, *p_h16h, *p_h16l, *p_imgh, *p_imgl;
    cudaGetSymbolAddress((void**)&p_h,    d_h);
    cudaGetSymbolAddress((void**)&p_tmp,  d_tmp);
    cudaGetSymbolAddress((void**)&p_cat,  d_cat);
    cudaGetSymbolAddress((void**)&p_a16h, d_a16h);
    cudaGetSymbolAddress((void**)&p_a16l, d_a16l);
    cudaGetSymbolAddress((void**)&p_h16h, d_h16h);
    cudaGetSymbolAddress((void**)&p_h16l, d_h16l);
    cudaGetSymbolAddress((void**)&p_imgh, d_imgh);
    cudaGetSymbolAddress((void**)&p_imgl, d_imgl);

    cudaFuncSetAttribute(gemm_tc<F_WRITEC>, cudaFuncAttributeMaxDynamicSharedMemorySize, SMEMSZ);
    cudaFuncSetAttribute(gemm_tc<F_BIAS | F_WRITEC | F_EMIT16>, cudaFuncAttributeMaxDynamicSharedMemorySize, SMEMSZ);
    cudaFuncSetAttribute(gemm_tc<F_ADDMAT | F_GRAPH | F_RELU_O | F_EMIT16>, cudaFuncAttributeMaxDynamicSharedMemorySize, SMEMSZ);
    cudaFuncSetAttribute(gemm_tc<F_BIAS | F_ADDMAT | F_WRITEC | F_EMIT16>, cudaFuncAttributeMaxDynamicSharedMemorySize, SMEMSZ);
    cudaFuncSetAttribute(gemm_tc<F_BIAS | F_RELU_O | F_WRITEC>, cudaFuncAttributeMaxDynamicSharedMemorySize, SMEMSZ);

    // weight prep
    wmu_kernel<<<Hh, 128>>>(Wm2, Wu1);
    prep_weights<<<dim3(64, 7), 256>>>(We2, Wm1, Wu1, Wu2, Wd1);

    // encoder
    enc1_kernel<<<2048, 128>>>(x, xmask, We1, be1);
    gemm_tc<F_BIAS | F_WRITEC | F_EMIT16><<<dim3(NB, 1), 256, SMEMSZ>>>(
        p_a16h, p_a16l, p_imgh, p_imgl, p_h, be2, nullptr, nullptr, p_h16h, p_h16l, Nn);

    // degrees
    zero_cnt_kernel<<<(Nn + 255) / 256, 256>>>();
    deg_kernel<<<1024, 256>>>(ei);
    invcnt_kernel<<<(Nn + 255) / 256, 256>>>();

    // graph statistics from h0 + constant projections
    zero_stats_kernel<<<(Gg * Hh + 255) / 256, 256>>>();
    init_stats_kernel<<<(Nn + 63) / 64, 128>>>(xmask, batch);
    gproj_kernel<<<Gg, 128>>>(Wu1);
    bcproj_kernel<<<Gg, 128>>>(Wu1, bu1, bm2);

    for (int r = 0; r < 3; r++) {
        // fused Ps|Pd|t1 = h @ [W_src | W_dst | U_h]
        gemm_tc<F_WRITEC><<<dim3(NB, 3), 256, SMEMSZ>>>(
            p_h16h, p_h16l, p_imgh + 1 * 16384, p_imgl + 1 * 16384, p_cat,
            nullptr, nullptr, nullptr, nullptr, nullptr, Nn);
        selfloop_kernel<<<(Nn * 32 + 255) / 256, 256>>>(bm1);
        edge_scatter_kernel<<<2048, 256>>>(ei, ea, Wm1, bm1);
        conv_rm_kernel<<<(Nn * 32 + 255) / 256, 256>>>();
        // u = relu(t1 + (rm/cnt)@Wmu + gproj[batch] + bcproj[batch]) -> a16
        gemm_tc<F_ADDMAT | F_GRAPH | F_RELU_O | F_EMIT16><<<dim3(NB, 1), 256, SMEMSZ>>>(
            p_a16h, p_a16l, p_imgh + 4 * 16384, p_imgl + 4 * 16384, nullptr,
            nullptr, p_cat + (size_t)2 * Nn * Hh, batch, p_a16h, p_a16l, Nn);
        // h = h + u@W_u2 + b_u2  (also emit h16)
        gemm_tc<F_BIAS | F_ADDMAT | F_WRITEC | F_EMIT16><<<dim3(NB, 1), 256, SMEMSZ>>>(
            p_a16h, p_a16l, p_imgh + 5 * 16384, p_imgl + 5 * 16384, p_h,
            bu2, p_h, nullptr, p_h16h, p_h16l, Nn);
        if (r < 2) {
            zero_gsum_kernel<<<(Gg * Hh + 255) / 256, 256>>>();
            graph_sum_kernel<<<(Nn + 63) / 64, 128>>>(batch);
            gproj_kernel<<<Gg, 128>>>(Wu1);
        }
    }

    // decoder
    gemm_tc<F_BIAS | F_RELU_O | F_WRITEC><<<dim3(NB, 1), 256, SMEMSZ>>>(
        p_h16h, p_h16l, p_imgh + 6 * 16384, p_imgl + 6 * 16384, p_tmp,
        bd1, nullptr, nullptr, nullptr, nullptr, Nn);
    dec2_kernel<<<(Nn * 32 + 255) / 256, 256>>>(Wd2, bd2, out);
}

// round 4
// speedup vs baseline: 1.6383x; 1.1395x over previous
#include <cuda_runtime.h>
#include <cuda_bf16.h>

#define Nn 50000
#define Hh 128
#define Ee 400000
#define Gg 8
#define NB 391            // ceil(Nn/128) tiles
#define GRIDX 296         // 148 SMs x 2 CTAs
typedef __nv_bfloat16 bf16;
typedef unsigned int u32;

// ---------------- scratch (static device globals; no allocation) ----------------
__device__ float d_h[Nn * Hh];
__device__ float d_tmp[Nn * Hh];
__device__ float d_cat[3 * Nn * Hh];        // Ps | Pd | t1
__device__ float d_rm[Nn * Hh];
__device__ bf16  d_imgh[7 * 128 * 128], d_imgl[7 * 128 * 128]; // W^T images [n][k]
__device__ int   d_cnt[Nn];
__device__ float d_invcnt[Nn];
__device__ float d_gsum[Gg * Hh], d_bcsum[Gg * Hh], d_gcnt[Gg], d_bccnt[Gg];
__device__ float d_gproj[Gg * Hh], d_bcproj[Gg * Hh];
__device__ float d_Wmu[Hh * Hh];

// ---------------- helpers ----------------
__device__ __forceinline__ u32 smem_u32(const void* p) {
    u32 a;
    asm("{ .reg .u64 t; cvta.to.shared.u64 t, %1; cvt.u32.u64 %0, t; }" : "=r"(a) : "l"(p));
    return a;
}
__device__ __forceinline__ void ldsm_x2(u32* r, u32 addr) {
    asm volatile("ldmatrix.sync.aligned.m8n8.x2.shared.b16 {%0,%1}, [%2];"
                 : "=r"(r[0]), "=r"(r[1]) : "r"(addr));
}
__device__ __forceinline__ void mma16816(float* c, const u32* a, const u32* b) {
    asm volatile("mma.sync.aligned.m16n8k16.row.col.f32.bf16.bf16.f32 "
                 "{%0,%1,%2,%3}, {%4,%5,%6,%7}, {%8,%9}, {%0,%1,%2,%3};"
                 : "+f"(c[0]), "+f"(c[1]), "+f"(c[2]), "+f"(c[3])
                 : "r"(a[0]), "r"(a[1]), "r"(a[2]), "r"(a[3]), "r"(b[0]), "r"(b[1]));
}
__device__ __forceinline__ void split2(float v, unsigned short& h, unsigned short& l) {
    bf16 hh = __float2bfloat16(v);
    bf16 ll = __float2bfloat16(v - __bfloat162float(hh));
    h = __bfloat16_as_ushort(hh);
    l = __bfloat16_as_ushort(ll);
}
// split a float2 into packed-hi (u32) and packed-lo (u32), low 16 bits = .x
__device__ __forceinline__ void split_pack(float2 v, u32& hi, u32& lo) {
    __nv_bfloat162 h2 = __float22bfloat162_rn(v);
    float2 hf = __bfloat1622float2(h2);
    __nv_bfloat162 l2 = __float22bfloat162_rn(make_float2(v.x - hf.x, v.y - hf.y));
    hi = *(u32*)&h2;
    lo = *(u32*)&l2;
}

// ---------------- tensor-core GEMM via mma.sync -------------------------------
// C[M,128] = split(A_fp32 [*invcnt]) @ (Bhi+Blo image) + epilogue
#define F_BIAS    1
#define F_ADDMAT  2
#define F_GRAPH   4
#define F_RELU_O  8
#define F_SCALE_A 16

#define PAD_B 272               // bytes per padded BT row (136 bf16)
#define SM_B_HI 0
#define SM_B_LO (128 * PAD_B)
#define SMEMSZ  (2 * 128 * PAD_B)   // 69632 B

template<int FLAGS>
__global__ void __launch_bounds__(256, 2) gemm_tc(
    const float* __restrict__ A,
    const bf16* __restrict__ Bhi, const bf16* __restrict__ Blo,
    float* __restrict__ C, const float* __restrict__ bias,
    const float* __restrict__ addmat, const int* __restrict__ batch, int M)
{
    extern __shared__ char smem[];
    const u32 sb = smem_u32(smem);
    const int tid = threadIdx.x;
    const int wid = tid >> 5, lane = tid & 31;
    const int yt = blockIdx.y;
    const bf16* bhi = Bhi + yt * 16384;
    const bf16* blo = Blo + yt * 16384;
    float* Cy = C + (size_t)yt * M * Hh;

    // stage B image (hi+lo) into padded smem once
#pragma unroll
    for (int i = 0; i < 8; i++) {
        int idx = tid + i * 256;          // 0..2047 chunks of 16B
        int r = idx >> 4, c = idx & 15;
        *(uint4*)(smem + SM_B_HI + r * PAD_B + c * 16) = ((const uint4*)bhi)[idx];
        *(uint4*)(smem + SM_B_LO + r * PAD_B + c * 16) = ((const uint4*)blo)[idx];
    }
    __syncthreads();

    const int wm = wid & 3;            // 4 warps in M (32 rows each)
    const int wn = wid >> 2;           // 2 warps in N (64 cols each)
    const int gid = lane >> 2, tig = lane & 3;
    const u32 bbase = (u32)((wn * 64 + (lane & 7)) * PAD_B + ((lane >> 3) & 1) * 16);

    for (int tile = blockIdx.x; tile < NB; tile += GRIDX) {
        const int row0 = tile * 128;

        // clamped row pointers for the 4 fragment rows this lane touches
        int rr[4];
        const float* pa[4];
        float sc[4];
#pragma unroll
        for (int j = 0; j < 4; j++) {
            int r = row0 + wm * 32 + gid + j * 8;
            if (r > M - 1) r = M - 1;
            rr[j] = r;
            pa[j] = A + (size_t)r * Hh + tig * 2;
            if (FLAGS & F_SCALE_A) sc[j] = d_invcnt[r];
        }

        float acc[2][8][4];
#pragma unroll
        for (int m = 0; m < 2; m++)
#pragma unroll
            for (int n = 0; n < 8; n++)
#pragma unroll
                for (int j = 0; j < 4; j++) acc[m][n][j] = 0.f;

#pragma unroll
        for (int ks = 0; ks < 8; ks++) {
            const int ko = ks * 16;
            u32 ah[2][4], al[2][4];
#pragma unroll
            for (int m = 0; m < 2; m++) {
                float2 v00 = *(const float2*)(pa[2 * m + 0] + ko);      // row gid,   k c
                float2 v10 = *(const float2*)(pa[2 * m + 1] + ko);      // row gid+8, k c
                float2 v01 = *(const float2*)(pa[2 * m + 0] + ko + 8);  // row gid,   k c+8
                float2 v11 = *(const float2*)(pa[2 * m + 1] + ko + 8);  // row gid+8, k c+8
                if (FLAGS & F_SCALE_A) {
                    v00.x *= sc[2 * m]; v00.y *= sc[2 * m];
                    v01.x *= sc[2 * m]; v01.y *= sc[2 * m];
                    v10.x *= sc[2 * m + 1]; v10.y *= sc[2 * m + 1];
                    v11.x *= sc[2 * m + 1]; v11.y *= sc[2 * m + 1];
                }
                split_pack(v00, ah[m][0], al[m][0]);
                split_pack(v10, ah[m][1], al[m][1]);
                split_pack(v01, ah[m][2], al[m][2]);
                split_pack(v11, ah[m][3], al[m][3]);
            }
#pragma unroll
            for (int nt = 0; nt < 8; nt++) {
                u32 bh[2], bl[2];
                u32 bo = bbase + (u32)(nt * 8 * PAD_B) + (u32)(ks * 32);
                ldsm_x2(bh, sb + SM_B_HI + bo);
                ldsm_x2(bl, sb + SM_B_LO + bo);
#pragma unroll
                for (int m = 0; m < 2; m++) {
                    mma16816(acc[m][nt], ah[m], bh);
                    mma16816(acc[m][nt], al[m], bh);
                    mma16816(acc[m][nt], ah[m], bl);
                }
            }
        }

        // epilogue from registers
#pragma unroll
        for (int m = 0; m < 2; m++) {
#pragma unroll
            for (int half = 0; half < 2; half++) {
                int grow = row0 + wm * 32 + m * 16 + half * 8 + gid;
                if (grow >= M) continue;
                int g = 0;
                if (FLAGS & F_GRAPH) g = batch[grow];
#pragma unroll
                for (int nt = 0; nt < 8; nt++) {
                    int col = wn * 64 + nt * 8 + tig * 2;
                    float v0 = acc[m][nt][half * 2 + 0];
                    float v1 = acc[m][nt][half * 2 + 1];
                    if (FLAGS & F_BIAS) {
                        float2 b2 = *(const float2*)(bias + col);
                        v0 += b2.x; v1 += b2.y;
                    }
                    if (FLAGS & F_ADDMAT) {
                        float2 m2 = *(const float2*)(addmat + (size_t)grow * Hh + col);
                        v0 += m2.x; v1 += m2.y;
                    }
                    if (FLAGS & F_GRAPH) {
                        float2 g2 = *(const float2*)(d_gproj + g * Hh + col);
                        float2 c2 = *(const float2*)(d_bcproj + g * Hh + col);
                        v0 += g2.x + c2.x; v1 += g2.y + c2.y;
                    }
                    if (FLAGS & F_RELU_O) { v0 = fmaxf(v0, 0.f); v1 = fmaxf(v1, 0.f); }
                    *(float2*)(Cy + (size_t)grow * Hh + col) = make_float2(v0, v1);
                }
            }
        }
    }
}

// ---------------- weight prep: W^T split into [n][k] images -------------------
__global__ void __launch_bounds__(256) prep_weights(
    const float* __restrict__ We2, const float* __restrict__ Wm1,
    const float* __restrict__ Wu1, const float* __restrict__ Wu2,
    const float* __restrict__ Wd1)
{
    int tile = blockIdx.y;
    int idx = blockIdx.x * 256 + threadIdx.x;   // 0..16383
    int n = idx >> 7, k = idx & 127;
    float v = 0.f;
    switch (tile) {
        case 0: v = We2[(size_t)k * Hh + n]; break;
        case 1: v = Wm1[(size_t)k * Hh + n]; break;           // W_m1 src half
        case 2: v = Wm1[(size_t)(128 + k) * Hh + n]; break;   // W_m1 dst half
        case 3: v = Wu1[(size_t)k * Hh + n]; break;           // U_h
        case 4: v = d_Wmu[(size_t)k * Hh + n]; break;         // W_m2 @ U_a
        case 5: v = Wu2[(size_t)k * Hh + n]; break;
        case 6: v = Wd1[(size_t)k * Hh + n]; break;
    }
    unsigned short h, l;
    split2(v, h, l);
    d_imgh[tile * 16384 + n * 128 + k] = __ushort_as_bfloat16(h);
    d_imgl[tile * 16384 + n * 128 + k] = __ushort_as_bfloat16(l);
}

// ---------------- encoder layer 1: d_tmp = relu([x|xm] @ W_e1 + b_e1) ---------
__global__ void __launch_bounds__(128) enc1_kernel(
    const float* __restrict__ x, const float* __restrict__ xmask,
    const float* __restrict__ We1, const float* __restrict__ be1)
{
    __shared__ float sW[8 * Hh];
    __shared__ float sb_[Hh];
    __shared__ float in[8];
    int f = threadIdx.x;
#pragma unroll
    for (int k = 0; k < 8; k++) sW[k * Hh + f] = We1[k * Hh + f];
    sb_[f] = be1[f];
    __syncthreads();
    for (int v = blockIdx.x; v < Nn; v += gridDim.x) {
        if (f < 5)      in[f] = x[v * 5 + f];
        else if (f < 8) in[f] = xmask[v * 3 + (f - 5)];
        __syncthreads();
        float s = sb_[f];
#pragma unroll
        for (int k = 0; k < 8; k++) s = fmaf(in[k], sW[k * Hh + f], s);
        d_tmp[(size_t)v * Hh + f] = fmaxf(s, 0.f);
        __syncthreads();
    }
}

// ---------------- degree / counts ----------------------------------------------
__global__ void zero_cnt_kernel() {
    int i = blockIdx.x * blockDim.x + threadIdx.x;
    if (i < Nn) d_cnt[i] = 0;
}
__global__ void deg_kernel(const int* __restrict__ ei) {
    for (int e = blockIdx.x * blockDim.x + threadIdx.x; e < Ee; e += gridDim.x * blockDim.x)
        atomicAdd(&d_cnt[ei[Ee + e]], 1);
}
__global__ void invcnt_kernel() {
    int i = blockIdx.x * blockDim.x + threadIdx.x;
    if (i < Nn) d_invcnt[i] = 1.0f / (float)(d_cnt[i] + 1);
}

// ---------------- graph stats ---------------------------------------------------
__global__ void zero_stats_kernel() {
    int i = blockIdx.x * blockDim.x + threadIdx.x;
    if (i < Gg * Hh) { d_gsum[i] = 0.f; d_bcsum[i] = 0.f; }
    if (i < Gg) { d_gcnt[i] = 0.f; d_bccnt[i] = 0.f; }
}
__global__ void zero_gsum_kernel() {
    int i = blockIdx.x * blockDim.x + threadIdx.x;
    if (i < Gg * Hh) d_gsum[i] = 0.f;
}
__global__ void __launch_bounds__(128) init_stats_kernel(
    const float* __restrict__ xmask, const int* __restrict__ batch)
{
    int f = threadIdx.x;
    int v0 = blockIdx.x * 64;
    if (v0 >= Nn) return;
    float acc = 0.f, accbc = 0.f, cacc = 0.f, bcacc = 0.f;
    int cur = batch[v0];
    for (int i = 0; i < 64; i++) {
        int v = v0 + i; if (v >= Nn) break;
        int g = batch[v];
        if (g != cur) {
            atomicAdd(&d_gsum[cur * Hh + f], acc);
            atomicAdd(&d_bcsum[cur * Hh + f], accbc);
            if (f == 0) { atomicAdd(&d_gcnt[cur], cacc); atomicAdd(&d_bccnt[cur], bcacc); }
            acc = accbc = cacc = bcacc = 0.f; cur = g;
        }
        float hv = d_h[(size_t)v * Hh + f];
        float bc = __ldg(xmask + v * 3 + 2);
        acc += hv; accbc += hv * bc;
        if (f == 0) { cacc += 1.f; bcacc += bc; }
    }
    atomicAdd(&d_gsum[cur * Hh + f], acc);
    atomicAdd(&d_bcsum[cur * Hh + f], accbc);
    if (f == 0) { atomicAdd(&d_gcnt[cur], cacc); atomicAdd(&d_bccnt[cur], bcacc); }
}
__global__ void __launch_bounds__(128) graph_sum_kernel(const int* __restrict__ batch)
{
    int f = threadIdx.x;
    int v0 = blockIdx.x * 64;
    if (v0 >= Nn) return;
    float acc = 0.f;
    int cur = batch[v0];
    for (int i = 0; i < 64; i++) {
        int v = v0 + i; if (v >= Nn) break;
        int g = batch[v];
        if (g != cur) { atomicAdd(&d_gsum[cur * Hh + f], acc); acc = 0.f; cur = g; }
        acc += d_h[(size_t)v * Hh + f];
    }
    atomicAdd(&d_gsum[cur * Hh + f], acc);
}
__global__ void __launch_bounds__(128) gproj_kernel(const float* __restrict__ Wu1)
{
    __shared__ float xg[Hh];
    int g = blockIdx.x, f = threadIdx.x;
    float c = fmaxf(d_gcnt[g], 1.f);
    xg[f] = d_gsum[g * Hh + f] / c;
    __syncthreads();
    float s = 0.f;
#pragma unroll 8
    for (int k = 0; k < Hh; k++) s = fmaf(xg[k], Wu1[(size_t)(256 + k) * Hh + f], s);
    d_gproj[g * Hh + f] = s;
}
__global__ void __launch_bounds__(128) bcproj_kernel(
    const float* __restrict__ Wu1, const float* __restrict__ bu1, const float* __restrict__ bm2)
{
    __shared__ float xbc[Hh];
    int g = blockIdx.x, f = threadIdx.x;
    float c = fmaxf(d_bccnt[g], 1.f);
    xbc[f] = d_bcsum[g * Hh + f] / c;
    __syncthreads();
    float s = bu1[f];
#pragma unroll 8
    for (int k = 0; k < Hh; k++) {
        s = fmaf(xbc[k],         Wu1[(size_t)(384 + k) * Hh + f], s);
        s = fmaf(__ldg(bm2 + k), Wu1[(size_t)(128 + k) * Hh + f], s);
    }
    d_bcproj[g * Hh + f] = s;
}
__global__ void __launch_bounds__(128) wmu_kernel(
    const float* __restrict__ Wm2, const float* __restrict__ Wu1)
{
    __shared__ float row[Hh];
    int k = blockIdx.x, f = threadIdx.x;
    row[f] = Wm2[(size_t)k * Hh + f];
    __syncthreads();
    float s = 0.f;
#pragma unroll 8
    for (int j = 0; j < Hh; j++) s = fmaf(row[j], Wu1[(size_t)(128 + j) * Hh + f], s);
    d_Wmu[(size_t)k * Hh + f] = s;
}

// ---------------- self-loop + edge scatter --------------------------------------
__global__ void selfloop_kernel(const float* __restrict__ bm1)
{
    int i = blockIdx.x * blockDim.x + threadIdx.x;
    if (i >= Nn * 32) return;
    int f4 = i & 31;
    const float4* PS = (const float4*)d_cat;
    const float4* PD = PS + (size_t)Nn * 32;
    float4 ps = PS[i];
    float4 pd = PD[i];
    float4 b = *(const float4*)(bm1 + f4 * 4);
    float4 v;
    v.x = fmaxf(ps.x + pd.x + b.x, 0.f);
    v.y = fmaxf(ps.y + pd.y + b.y, 0.f);
    v.z = fmaxf(ps.z + pd.z + b.z, 0.f);
    v.w = fmaxf(ps.w + pd.w + b.w, 0.f);
    ((float4*)d_rm)[i] = v;
}

__device__ __forceinline__ void red_add_v4(float* p, float4 v) {
    asm volatile("red.global.add.v4.f32 [%0], {%1,%2,%3,%4};"
                 :: "l"(p), "f"(v.x), "f"(v.y), "f"(v.z), "f"(v.w) : "memory");
}
__global__ void __launch_bounds__(256) edge_scatter_kernel(
    const int* __restrict__ ei, const float* __restrict__ ea,
    const float* __restrict__ Wm1, const float* __restrict__ bm1)
{
    __shared__ float4 sW0[32], sW1[32], sW2[32], sB[32];
    int tid = threadIdx.x;
    if (tid < 32) {
        sW0[tid] = *(const float4*)(Wm1 + (size_t)256 * Hh + tid * 4);
        sW1[tid] = *(const float4*)(Wm1 + (size_t)257 * Hh + tid * 4);
        sW2[tid] = *(const float4*)(Wm1 + (size_t)258 * Hh + tid * 4);
        sB[tid]  = *(const float4*)(bm1 + tid * 4);
    }
    __syncthreads();
    int lane = tid & 31;
    int warp = blockIdx.x * (blockDim.x >> 5) + (tid >> 5);
    int nwarp = gridDim.x * (blockDim.x >> 5);
    float4 w0 = sW0[lane], w1 = sW1[lane], w2 = sW2[lane], bb = sB[lane];
    const float* Ps = d_cat;
    const float* Pd = d_cat + (size_t)Nn * Hh;
    for (int e = warp; e < Ee; e += nwarp) {
        int s = __ldg(ei + e);
        int d = __ldg(ei + Ee + e);
        float a0 = __ldg(ea + 3 * e), a1 = __ldg(ea + 3 * e + 1), a2 = __ldg(ea + 3 * e + 2);
        float4 ps = *(const float4*)(Ps + (size_t)s * Hh + lane * 4);
        float4 pd = *(const float4*)(Pd + (size_t)d * Hh + lane * 4);
        float4 v;
        v.x = fmaxf(ps.x + pd.x + a0 * w0.x + a1 * w1.x + a2 * w2.x + bb.x, 0.f);
        v.y = fmaxf(ps.y + pd.y + a0 * w0.y + a1 * w1.y + a2 * w2.y + bb.y, 0.f);
        v.z = fmaxf(ps.z + pd.z + a0 * w0.z + a1 * w1.z + a2 * w2.z + bb.z, 0.f);
        v.w = fmaxf(ps.w + pd.w + a0 * w0.w + a1 * w1.w + a2 * w2.w + bb.w, 0.f);
        red_add_v4(d_rm + (size_t)d * Hh + lane * 4, v);
    }
}

// ---------------- decoder layer 2 -------------------------------------------------
__global__ void __launch_bounds__(256) dec2_kernel(
    const float* __restrict__ Wd2, const float* __restrict__ bd2, float* __restrict__ out)
{
    int gt = blockIdx.x * blockDim.x + threadIdx.x;
    int w = gt >> 5, lane = gt & 31;
    if (w >= Nn) return;
    float4 v = ((const float4*)d_tmp)[(size_t)w * 32 + lane];
    float s0 = 0.f, s1 = 0.f, s2 = 0.f;
    int k0 = lane * 4;
    float av[4] = {v.x, v.y, v.z, v.w};
#pragma unroll
    for (int i = 0; i < 4; i++) {
        int k = k0 + i;
        float a = av[i];
        s0 = fmaf(a, __ldg(Wd2 + k * 3 + 0), s0);
        s1 = fmaf(a, __ldg(Wd2 + k * 3 + 1), s1);
        s2 = fmaf(a, __ldg(Wd2 + k * 3 + 2), s2);
    }
#pragma unroll
    for (int off = 16; off; off >>= 1) {
        s0 += __shfl_xor_sync(0xffffffffu, s0, off);
        s1 += __shfl_xor_sync(0xffffffffu, s1, off);
        s2 += __shfl_xor_sync(0xffffffffu, s2, off);
    }
    if (lane == 0) {
        out[w * 3 + 0] = s0 + __ldg(bd2 + 0);
        out[w * 3 + 1] = s1 + __ldg(bd2 + 1);
        out[w * 3 + 2] = s2 + __ldg(bd2 + 2);
    }
}

// ---------------- host orchestration ----------------------------------------------
extern "C" void kernel_launch(void* const* d_in, const int* in_sizes, int n_in,
                              void* d_out, int out_size)
{
    const float* x     = (const float*)d_in[0];
    const float* xmask = (const float*)d_in[1];
    const float* ea    = (const float*)d_in[2];
    const float* We1 = (const float*)d_in[4];
    const float* be1 = (const float*)d_in[5];
    const float* We2 = (const float*)d_in[6];
    const float* be2 = (const float*)d_in[7];
    const float* Wm1 = (const float*)d_in[8];
    const float* bm1 = (const float*)d_in[9];
    const float* Wm2 = (const float*)d_in[10];
    const float* bm2 = (const float*)d_in[11];
    const float* Wu1 = (const float*)d_in[12];
    const float* bu1 = (const float*)d_in[13];
    const float* Wu2 = (const float*)d_in[14];
    const float* bu2 = (const float*)d_in[15];
    const float* Wd1 = (const float*)d_in[16];
    const float* bd1 = (const float*)d_in[17];
    const float* Wd2 = (const float*)d_in[18];
    const float* bd2 = (const float*)d_in[19];
    const int*   ei    = (const int*)d_in[20];
    const int*   batch = (const int*)d_in[21];
    float* out = (float*)d_out;

    float *p_h, *p_tmp, *p_cat, *p_rm;
    bf16 *p_imgh, *p_imgl;
    cudaGetSymbolAddress((void**)&p_h,    d_h);
    cudaGetSymbolAddress((void**)&p_tmp,  d_tmp);
    cudaGetSymbolAddress((void**)&p_cat,  d_cat);
    cudaGetSymbolAddress((void**)&p_rm,   d_rm);
    cudaGetSymbolAddress((void**)&p_imgh, d_imgh);
    cudaGetSymbolAddress((void**)&p_imgl, d_imgl);

    cudaFuncSetAttribute(gemm_tc<F_BIAS>, cudaFuncAttributeMaxDynamicSharedMemorySize, SMEMSZ);
    cudaFuncSetAttribute(gemm_tc<0>, cudaFuncAttributeMaxDynamicSharedMemorySize, SMEMSZ);
    cudaFuncSetAttribute(gemm_tc<F_SCALE_A | F_ADDMAT | F_GRAPH | F_RELU_O>, cudaFuncAttributeMaxDynamicSharedMemorySize, SMEMSZ);
    cudaFuncSetAttribute(gemm_tc<F_BIAS | F_ADDMAT>, cudaFuncAttributeMaxDynamicSharedMemorySize, SMEMSZ);
    cudaFuncSetAttribute(gemm_tc<F_BIAS | F_RELU_O>, cudaFuncAttributeMaxDynamicSharedMemorySize, SMEMSZ);

    // weight prep
    wmu_kernel<<<Hh, 128>>>(Wm2, Wu1);
    prep_weights<<<dim3(64, 7), 256>>>(We2, Wm1, Wu1, Wu2, Wd1);

    // encoder: enc1 -> d_tmp (fp32), then h0 = d_tmp @ We2 + be2
    enc1_kernel<<<2048, 128>>>(x, xmask, We1, be1);
    gemm_tc<F_BIAS><<<dim3(GRIDX, 1), 256, SMEMSZ>>>(
        p_tmp, p_imgh, p_imgl, p_h, be2, nullptr, nullptr, Nn);

    // degrees
    zero_cnt_kernel<<<(Nn + 255) / 256, 256>>>();
    deg_kernel<<<1024, 256>>>(ei);
    invcnt_kernel<<<(Nn + 255) / 256, 256>>>();

    // graph statistics from h0 + constant projections
    zero_stats_kernel<<<(Gg * Hh + 255) / 256, 256>>>();
    init_stats_kernel<<<(Nn + 63) / 64, 128>>>(xmask, batch);
    gproj_kernel<<<Gg, 128>>>(Wu1);
    bcproj_kernel<<<Gg, 128>>>(Wu1, bu1, bm2);

    for (int r = 0; r < 3; r++) {
        // fused Ps|Pd|t1 = h @ [W_src | W_dst | U_h]
        gemm_tc<0><<<dim3(GRIDX, 3), 256, SMEMSZ>>>(
            p_h, p_imgh + 1 * 16384, p_imgl + 1 * 16384, p_cat,
            nullptr, nullptr, nullptr, Nn);
        selfloop_kernel<<<(Nn * 32 + 255) / 256, 256>>>(bm1);
        edge_scatter_kernel<<<2048, 256>>>(ei, ea, Wm1, bm1);
        // u = relu(t1 + (rm*invcnt)@Wmu + gproj[batch] + bcproj[batch]) -> d_tmp
        gemm_tc<F_SCALE_A | F_ADDMAT | F_GRAPH | F_RELU_O><<<dim3(GRIDX, 1), 256, SMEMSZ>>>(
            p_rm, p_imgh + 4 * 16384, p_imgl + 4 * 16384, p_tmp,
            nullptr, p_cat + (size_t)2 * Nn * Hh, batch, Nn);
        // h = h + u@W_u2 + b_u2
        gemm_tc<F_BIAS | F_ADDMAT><<<dim3(GRIDX, 1), 256, SMEMSZ>>>(
            p_tmp, p_imgh + 5 * 16384, p_imgl + 5 * 16384, p_h,
            bu2, p_h, nullptr, Nn);
        if (r < 2) {
            zero_gsum_kernel<<<(Gg * Hh + 255) / 256, 256>>>();
            graph_sum_kernel<<<(Nn + 63) / 64, 128>>>(batch);
            gproj_kernel<<<Gg, 128>>>(Wu1);
        }
    }

    // decoder
    gemm_tc<F_BIAS | F_RELU_O><<<dim3(GRIDX, 1), 256, SMEMSZ>>>(
        p_h, p_imgh + 6 * 16384, p_imgl + 6 * 16384, p_tmp,
        bd1, nullptr, nullptr, Nn);
    dec2_kernel<<<(Nn * 32 + 255) / 256, 256>>>(Wd2, bd2, out);
}